// round 5
// baseline (speedup 1.0000x reference)
#include <cuda_runtime.h>
#include <math_constants.h>

// Problem constants
#define NROWS 262144
#define DIMQ  128
#define MFEAT 256
#define SCALE 0.29730177875068026f   // 128^-0.25
#define INV_SQRT_M 0.0625f           // 1/sqrt(256)
#define PHI_EPS 1e-4f

// phase1 tiling
#define P1_THREADS 128
#define P1_ROWS    128
#define P1_SMEM_FLOATS (DIMQ*MFEAT + P1_ROWS*129)   // omega + padded X tile
#define P1_SMEM_BYTES  (P1_SMEM_FLOATS*4)           // 197120 B

// kp pass tiling
#define KP_BLOCKS 1024
#define KP_ROWS_PER_BLOCK (NROWS / KP_BLOCKS)       // 256

// Scratch (device globals: allocation-free per harness rules)
__device__ float g_UK[(size_t)NROWS * MFEAT];   // U_K - h_K, later overwritten with Kp
__device__ float g_UQ[(size_t)NROWS * MFEAT];   // U_Q - h_Q
__device__ float g_part[KP_BLOCKS * MFEAT];     // per-block Kp column partial sums
__device__ float g_ksum[MFEAT];                 // column sums of Kp
__device__ unsigned g_kmax_bits;                // ordered-encoded global max of U_K

// Monotonic float<->uint encoding for atomicMax on floats (incl. negatives)
__device__ __forceinline__ unsigned fenc(float f) {
    unsigned u = __float_as_uint(f);
    return (u >> 31) ? ~u : (u | 0x80000000u);
}
__device__ __forceinline__ float fdec(unsigned u) {
    return (u >> 31) ? __uint_as_float(u & 0x7fffffffu) : __uint_as_float(~u);
}

__global__ void init_kernel() {
    g_kmax_bits = 0u;   // below any real encoding
}

// ---------------------------------------------------------------------------
// phase1: U = (X * SCALE) @ omega ; store (U - h) to Uout.
// IS_K: additionally track global max of raw U via atomicMax.
// block: 128 threads, one row per thread, 128 rows per block.
// ---------------------------------------------------------------------------
template <bool IS_K>
__global__ __launch_bounds__(P1_THREADS)
void phase1_kernel(const float* __restrict__ X,
                   const float* __restrict__ omega,
                   float* __restrict__ Uout)
{
    extern __shared__ float smem[];
    float* sOm = smem;                       // [128][256]
    float* sX  = smem + DIMQ * MFEAT;        // [128][129] padded

    const int tid = threadIdx.x;
    const size_t row0 = (size_t)blockIdx.x * P1_ROWS;

    // cooperative loads (coalesced)
    #pragma unroll 8
    for (int idx = tid; idx < DIMQ * MFEAT; idx += P1_THREADS)
        sOm[idx] = omega[idx];
    #pragma unroll 4
    for (int r = 0; r < P1_ROWS; r++)
        sX[r * 129 + tid] = X[(row0 + r) * DIMQ + tid] * SCALE;
    __syncthreads();

    const float* xr = sX + tid * 129;

    // h = 0.5 * sum(xs^2)   (since sum(X^2)/(2*sqrt(d)) = 0.5*sum((X*d^-1/4)^2))
    float h = 0.f;
    #pragma unroll 8
    for (int i = 0; i < DIMQ; i++) { float v = xr[i]; h = fmaf(v, v, h); }
    h *= 0.5f;

    float umax = -CUDART_INF_F;
    float* outRow = Uout + (row0 + tid) * MFEAT;

    #pragma unroll 1
    for (int jc = 0; jc < MFEAT / 32; jc++) {
        float4 acc[8];
        #pragma unroll
        for (int q = 0; q < 8; q++) acc[q] = make_float4(0.f, 0.f, 0.f, 0.f);

        const float* omBase = sOm + jc * 32;
        #pragma unroll 4
        for (int i = 0; i < DIMQ; i++) {
            float xv = xr[i];
            const float4* o = reinterpret_cast<const float4*>(omBase + i * MFEAT);
            #pragma unroll
            for (int q = 0; q < 8; q++) {
                float4 ov = o[q];
                acc[q].x = fmaf(xv, ov.x, acc[q].x);
                acc[q].y = fmaf(xv, ov.y, acc[q].y);
                acc[q].z = fmaf(xv, ov.z, acc[q].z);
                acc[q].w = fmaf(xv, ov.w, acc[q].w);
            }
        }
        #pragma unroll
        for (int q = 0; q < 8; q++) {
            float u0 = acc[q].x, u1 = acc[q].y, u2 = acc[q].z, u3 = acc[q].w;
            if (IS_K) {
                umax = fmaxf(umax, fmaxf(fmaxf(u0, u1), fmaxf(u2, u3)));
            }
            int j = jc * 32 + q * 4;
            outRow[j + 0] = u0 - h;
            outRow[j + 1] = u1 - h;
            outRow[j + 2] = u2 - h;
            outRow[j + 3] = u3 - h;
        }
    }

    if (IS_K) {
        // warp max then one atomic per warp (order-independent => deterministic)
        #pragma unroll
        for (int o = 16; o > 0; o >>= 1)
            umax = fmaxf(umax, __shfl_xor_sync(0xffffffffu, umax, o));
        if ((tid & 31) == 0)
            atomicMax(&g_kmax_bits, fenc(umax));
    }
}

// ---------------------------------------------------------------------------
// kp: Kp = (exp(U' - gmax) + eps)/sqrt(m), overwrite g_UK, per-block column
// partial sums (deterministic). thread t owns column t.
// ---------------------------------------------------------------------------
__global__ __launch_bounds__(MFEAT)
void kp_kernel()
{
    const int tid = threadIdx.x;
    const float gmax = fdec(g_kmax_bits);
    const size_t base = (size_t)blockIdx.x * KP_ROWS_PER_BLOCK * MFEAT + tid;

    float psum = 0.f;
    #pragma unroll 4
    for (int r = 0; r < KP_ROWS_PER_BLOCK; r++) {
        size_t idx = base + (size_t)r * MFEAT;
        float u = g_UK[idx];
        float kp = (__expf(u - gmax) + PHI_EPS) * INV_SQRT_M;
        g_UK[idx] = kp;
        psum += kp;
    }
    g_part[blockIdx.x * MFEAT + tid] = psum;
}

// 1 block, 1024 threads: 4 slices x 256 columns, then combine
__global__ __launch_bounds__(1024)
void ksum_kernel()
{
    __shared__ float red[4][MFEAT];
    const int col = threadIdx.x & (MFEAT - 1);
    const int slice = threadIdx.x >> 8;           // 0..3
    const int per = KP_BLOCKS / 4;                // 256 blocks per slice

    float s = 0.f;
    #pragma unroll 8
    for (int b = 0; b < per; b++)
        s += g_part[(slice * per + b) * MFEAT + col];
    red[slice][col] = s;
    __syncthreads();
    if (slice == 0)
        g_ksum[col] = red[0][col] + red[1][col] + red[2][col] + red[3][col];
}

// ---------------------------------------------------------------------------
// final: warp per row. Row-max of U'_Q, Qp, w = <Qp,Kp>, norm = <Qp,ksum>+1e-8,
// out = (w/norm) * V.
// ---------------------------------------------------------------------------
__global__ __launch_bounds__(256)
void final_kernel(const float* __restrict__ V, float* __restrict__ out)
{
    const int lane = threadIdx.x & 31;
    const int warp = threadIdx.x >> 5;
    const size_t row = (size_t)blockIdx.x * 8 + warp;
    const size_t ub = row * MFEAT + lane;

    float u[8];
    #pragma unroll
    for (int t = 0; t < 8; t++) u[t] = g_UQ[ub + t * 32];

    float m = u[0];
    #pragma unroll
    for (int t = 1; t < 8; t++) m = fmaxf(m, u[t]);
    #pragma unroll
    for (int o = 16; o > 0; o >>= 1)
        m = fmaxf(m, __shfl_xor_sync(0xffffffffu, m, o));

    float w = 0.f, nrm = 0.f;
    #pragma unroll
    for (int t = 0; t < 8; t++) {
        float qp = (__expf(u[t] - m) + PHI_EPS) * INV_SQRT_M;
        float kp = g_UK[ub + t * 32];
        float ks = g_ksum[lane + t * 32];
        w   = fmaf(qp, kp, w);
        nrm = fmaf(qp, ks, nrm);
    }
    #pragma unroll
    for (int o = 16; o > 0; o >>= 1) {
        w   += __shfl_xor_sync(0xffffffffu, w, o);
        nrm += __shfl_xor_sync(0xffffffffu, nrm, o);
    }
    float scale = w / (nrm + 1e-8f);

    const size_t vb = row * DIMQ + lane;
    #pragma unroll
    for (int c = 0; c < 4; c++)
        out[vb + c * 32] = scale * V[vb + c * 32];
}

extern "C" void kernel_launch(void* const* d_in, const int* in_sizes, int n_in,
                              void* d_out, int out_size)
{
    const float* Q     = (const float*)d_in[0];
    const float* K     = (const float*)d_in[1];
    const float* V     = (const float*)d_in[2];
    const float* omega = (const float*)d_in[3];
    float* out = (float*)d_out;

    cudaFuncSetAttribute(phase1_kernel<true>,
                         cudaFuncAttributeMaxDynamicSharedMemorySize, P1_SMEM_BYTES);
    cudaFuncSetAttribute(phase1_kernel<false>,
                         cudaFuncAttributeMaxDynamicSharedMemorySize, P1_SMEM_BYTES);

    init_kernel<<<1, 1>>>();
    phase1_kernel<true ><<<NROWS / P1_ROWS, P1_THREADS, P1_SMEM_BYTES>>>(K, omega, g_UK);
    phase1_kernel<false><<<NROWS / P1_ROWS, P1_THREADS, P1_SMEM_BYTES>>>(Q, omega, g_UQ);
    kp_kernel<<<KP_BLOCKS, MFEAT>>>();
    ksum_kernel<<<1, 1024>>>();
    final_kernel<<<NROWS / 8, 256>>>(V, out);
}

// round 9
// speedup vs baseline: 59.0995x; 59.0995x over previous
#include <cuda_runtime.h>
#include <math_constants.h>

typedef unsigned long long ull;

// Problem constants
#define NROWS 262144
#define DIMQ  128
#define MFEAT 256
#define SCALE 0.29730177875068026f   // 128^-0.25
#define INV_SQRT_M 0.0625f           // 1/sqrt(256)
#define PHI_EPS 1e-4f

// GEMM tiling: BM=64 rows x BN=256 (full width), 256 threads, warp owns 8 rows,
// lane owns cols [lane*8, lane*8+8). K=128 streamed in 8 chunks of 16.
#define BM 64
#define GEMM_THREADS 256
#define GEMM_BLOCKS (NROWS / BM)            // 4096
#define SX_STRIDE 132                       // 128 + 4 pad (row-major X tile)
#define OM_CHUNK_FLOATS (16 * MFEAT)        // 4096
#define SMEM_FLOATS (BM * SX_STRIDE + 2 * OM_CHUNK_FLOATS)
#define SMEM_BYTES  (SMEM_FLOATS * 4)       // 66560 B -> 2 CTAs/SM

// kp pass
#define KP_BLOCKS 1024
#define KP_ROWS_PER_BLOCK (NROWS / KP_BLOCKS)   // 256

// Scratch (device globals: allocation-free). g_UK holds U'_K then Kp.
__device__ float g_UK[(size_t)NROWS * MFEAT];
__device__ float g_part[KP_BLOCKS * MFEAT];
__device__ float g_ksum[MFEAT];
__device__ unsigned g_kmax_bits;

// Monotonic float<->uint encoding for atomicMax on floats
__device__ __forceinline__ unsigned fenc(float f) {
    unsigned u = __float_as_uint(f);
    return (u >> 31) ? ~u : (u | 0x80000000u);
}
__device__ __forceinline__ float fdec(unsigned u) {
    return (u >> 31) ? __uint_as_float(u & 0x7fffffffu) : __uint_as_float(~u);
}

// Packed fp32x2 FMA (Blackwell FFMA2 — only reachable via PTX)
__device__ __forceinline__ ull fma2(ull a, ull b, ull c) {
    ull d;
    asm("fma.rn.f32x2 %0, %1, %2, %3;" : "=l"(d) : "l"(a), "l"(b), "l"(c));
    return d;
}
__device__ __forceinline__ ull pack2(float lo, float hi) {
    ull r;
    asm("mov.b64 %0, {%1, %2};" : "=l"(r) : "r"(__float_as_uint(lo)), "r"(__float_as_uint(hi)));
    return r;
}
__device__ __forceinline__ void unpack2(ull p, float& lo, float& hi) {
    unsigned a, b;
    asm("mov.b64 {%0, %1}, %2;" : "=r"(a), "=r"(b) : "l"(p));
    lo = __uint_as_float(a);
    hi = __uint_as_float(b);
}

__global__ void init_kernel() { g_kmax_bits = 0u; }

// ---------------------------------------------------------------------------
// Fused GEMM: U = (X*SCALE) @ omega, h folded in.
//  IS_K: store U-h to g_UK, track global max of raw U (atomicMax, deterministic).
// !IS_K: full Q epilogue in-registers: row-max, Qp, w=<Qp,Kp>, nrm=<Qp,ksum>,
//        out = (w/nrm)*V. No U_Q scratch traffic at all.
// ---------------------------------------------------------------------------
template <bool IS_K>
__global__ __launch_bounds__(GEMM_THREADS, 2)
void gemm_kernel(const float* __restrict__ X,
                 const float* __restrict__ omega,
                 const float* __restrict__ V,
                 float* __restrict__ out)
{
    extern __shared__ float smem[];
    float* sX  = smem;                       // [64][132] row-major, scaled
    float* sOm = smem + BM * SX_STRIDE;      // [2][16][256]

    const int tid  = threadIdx.x;
    const int lane = tid & 31;
    const int w    = tid >> 5;               // warp 0..7 -> rows w*8..w*8+7
    const size_t row0 = (size_t)blockIdx.x * BM;

    // Load X tile (scaled), coalesced; 8 float4 per thread.
    {
        const float4* Xg = (const float4*)(X + row0 * DIMQ);
        #pragma unroll
        for (int q = 0; q < 8; q++) {
            int f = tid + q * GEMM_THREADS;  // f4 index: r = f/32, c4 = f%32
            float4 v = Xg[f];
            v.x *= SCALE; v.y *= SCALE; v.z *= SCALE; v.w *= SCALE;
            int r = f >> 5, c4 = f & 31;
            *(float4*)(sX + r * SX_STRIDE + c4 * 4) = v;
        }
    }

    // Prefetch omega chunk 0 into registers (4 float4 / thread)
    float4 pf[4];
    {
        const float4* Og = (const float4*)omega;
        #pragma unroll
        for (int q = 0; q < 4; q++) pf[q] = Og[tid + q * GEMM_THREADS];
    }
    __syncthreads();

    // h per warp row (all lanes end up with h[i]); conflict-free LDS.
    float h[8];
    #pragma unroll
    for (int i = 0; i < 8; i++) {
        const float* xr = sX + (size_t)(w * 8 + i) * SX_STRIDE;
        float s = 0.f;
        #pragma unroll
        for (int c = 0; c < 4; c++) { float v = xr[lane + c * 32]; s = fmaf(v, v, s); }
        #pragma unroll
        for (int o = 16; o > 0; o >>= 1) s += __shfl_xor_sync(0xffffffffu, s, o);
        h[i] = 0.5f * s;
    }

    // Accumulators: acc[i][jp] = (u[row i][lane*8+2jp], u[row i][lane*8+2jp+1])
    ull acc[8][4];
    #pragma unroll
    for (int i = 0; i < 8; i++)
        #pragma unroll
        for (int jp = 0; jp < 4; jp++) acc[i][jp] = 0ull;

    // Mainloop: 8 chunks of BK=16, double-buffered omega.
    #pragma unroll 1
    for (int chunk = 0; chunk < 8; chunk++) {
        float* so = sOm + (chunk & 1) * OM_CHUNK_FLOATS;
        // Commit prefetched chunk to smem (coalesced, conflict-free).
        #pragma unroll
        for (int q = 0; q < 4; q++)
            *(float4*)(so + (size_t)(tid + q * GEMM_THREADS) * 4) = pf[q];
        __syncthreads();

        // Issue next chunk's global loads early (hidden under compute).
        if (chunk < 7) {
            const float4* Og = (const float4*)(omega + (size_t)(chunk + 1) * 16 * MFEAT);
            #pragma unroll
            for (int q = 0; q < 4; q++) pf[q] = Og[tid + q * GEMM_THREADS];
        }

        #pragma unroll
        for (int kk = 0; kk < 16; kk++) {
            const int kg = chunk * 16 + kk;
            const ulonglong2* bq =
                (const ulonglong2*)(so + kk * MFEAT + lane * 8);
            ulonglong2 bA = bq[0], bB = bq[1];
            #pragma unroll
            for (int i = 0; i < 8; i++) {
                float a = sX[(size_t)(w * 8 + i) * SX_STRIDE + kg];  // broadcast LDS
                ull ad = pack2(a, a);
                acc[i][0] = fma2(ad, bA.x, acc[i][0]);
                acc[i][1] = fma2(ad, bA.y, acc[i][1]);
                acc[i][2] = fma2(ad, bB.x, acc[i][2]);
                acc[i][3] = fma2(ad, bB.y, acc[i][3]);
            }
        }
        __syncthreads();
    }

    if (IS_K) {
        // --- K epilogue: store U-h coalesced, track raw-U global max ---
        float umax = -CUDART_INF_F;
        #pragma unroll
        for (int i = 0; i < 8; i++) {
            float u[8];
            #pragma unroll
            for (int jp = 0; jp < 4; jp++) unpack2(acc[i][jp], u[2 * jp], u[2 * jp + 1]);
            #pragma unroll
            for (int j = 0; j < 8; j++) umax = fmaxf(umax, u[j]);
            const float hi_ = h[i];
            const size_t row = row0 + w * 8 + i;
            float4* dst = (float4*)(g_UK + row * MFEAT + lane * 8);
            dst[0] = make_float4(u[0] - hi_, u[1] - hi_, u[2] - hi_, u[3] - hi_);
            dst[1] = make_float4(u[4] - hi_, u[5] - hi_, u[6] - hi_, u[7] - hi_);
        }
        #pragma unroll
        for (int o = 16; o > 0; o >>= 1)
            umax = fmaxf(umax, __shfl_xor_sync(0xffffffffu, umax, o));
        if (lane == 0) atomicMax(&g_kmax_bits, fenc(umax));
    } else {
        // --- Q epilogue: softmax-feature + weighting + output, in-registers ---
        float ks[8];
        {
            const float4* kg = (const float4*)(g_ksum + lane * 8);
            float4 k0 = kg[0], k1 = kg[1];
            ks[0] = k0.x; ks[1] = k0.y; ks[2] = k0.z; ks[3] = k0.w;
            ks[4] = k1.x; ks[5] = k1.y; ks[6] = k1.z; ks[7] = k1.w;
        }
        #pragma unroll
        for (int i = 0; i < 8; i++) {
            float u[8];
            #pragma unroll
            for (int jp = 0; jp < 4; jp++) unpack2(acc[i][jp], u[2 * jp], u[2 * jp + 1]);
            const float hi_ = h[i];
            #pragma unroll
            for (int j = 0; j < 8; j++) u[j] -= hi_;

            float m = u[0];
            #pragma unroll
            for (int j = 1; j < 8; j++) m = fmaxf(m, u[j]);
            #pragma unroll
            for (int o = 16; o > 0; o >>= 1)
                m = fmaxf(m, __shfl_xor_sync(0xffffffffu, m, o));

            const size_t row = row0 + w * 8 + i;
            const float4* kpg = (const float4*)(g_UK + row * MFEAT + lane * 8);
            float4 kp0 = kpg[0], kp1 = kpg[1];
            float kp[8] = { kp0.x, kp0.y, kp0.z, kp0.w, kp1.x, kp1.y, kp1.z, kp1.w };

            float wv = 0.f, nrm = 0.f;
            #pragma unroll
            for (int j = 0; j < 8; j++) {
                float qp = (__expf(u[j] - m) + PHI_EPS) * INV_SQRT_M;
                wv  = fmaf(qp, kp[j], wv);
                nrm = fmaf(qp, ks[j], nrm);
            }
            #pragma unroll
            for (int o = 16; o > 0; o >>= 1) {
                wv  += __shfl_xor_sync(0xffffffffu, wv, o);
                nrm += __shfl_xor_sync(0xffffffffu, nrm, o);
            }
            const float scale = wv / (nrm + 1e-8f);

            const size_t vb = row * DIMQ + lane;
            #pragma unroll
            for (int c = 0; c < 4; c++)
                out[vb + c * 32] = scale * V[vb + c * 32];
        }
    }
}

// ---------------------------------------------------------------------------
// kp: Kp = (exp(U' - gmax) + eps)/sqrt(m), overwrite g_UK, per-block column
// partial sums (deterministic). Already at DRAM roofline (~86us).
// ---------------------------------------------------------------------------
__global__ __launch_bounds__(MFEAT)
void kp_kernel()
{
    const int tid = threadIdx.x;
    const float gmax = fdec(g_kmax_bits);
    const size_t base = (size_t)blockIdx.x * KP_ROWS_PER_BLOCK * MFEAT + tid;

    float psum = 0.f;
    #pragma unroll 4
    for (int r = 0; r < KP_ROWS_PER_BLOCK; r++) {
        size_t idx = base + (size_t)r * MFEAT;
        float u = g_UK[idx];
        float kp = (__expf(u - gmax) + PHI_EPS) * INV_SQRT_M;
        g_UK[idx] = kp;
        psum += kp;
    }
    g_part[blockIdx.x * MFEAT + tid] = psum;
}

// 1 block, 1024 threads: 4 slices x 256 columns, then combine.
__global__ __launch_bounds__(1024)
void ksum_kernel()
{
    __shared__ float red[4][MFEAT];
    const int col = threadIdx.x & (MFEAT - 1);
    const int slice = threadIdx.x >> 8;
    const int per = KP_BLOCKS / 4;

    float s = 0.f;
    #pragma unroll 8
    for (int b = 0; b < per; b++)
        s += g_part[(slice * per + b) * MFEAT + col];
    red[slice][col] = s;
    __syncthreads();
    if (slice == 0)
        g_ksum[col] = red[0][col] + red[1][col] + red[2][col] + red[3][col];
}

extern "C" void kernel_launch(void* const* d_in, const int* in_sizes, int n_in,
                              void* d_out, int out_size)
{
    const float* Q     = (const float*)d_in[0];
    const float* K     = (const float*)d_in[1];
    const float* V     = (const float*)d_in[2];
    const float* omega = (const float*)d_in[3];
    float* out = (float*)d_out;

    cudaFuncSetAttribute(gemm_kernel<true>,
                         cudaFuncAttributeMaxDynamicSharedMemorySize, SMEM_BYTES);
    cudaFuncSetAttribute(gemm_kernel<false>,
                         cudaFuncAttributeMaxDynamicSharedMemorySize, SMEM_BYTES);

    init_kernel<<<1, 1>>>();
    gemm_kernel<true ><<<GEMM_BLOCKS, GEMM_THREADS, SMEM_BYTES>>>(K, omega, nullptr, nullptr);
    kp_kernel<<<KP_BLOCKS, MFEAT>>>();
    ksum_kernel<<<1, 1024>>>();
    gemm_kernel<false><<<GEMM_BLOCKS, GEMM_THREADS, SMEM_BYTES>>>(Q, omega, V, out);
}

// round 13
// speedup vs baseline: 59.2406x; 1.0024x over previous
#include <cuda_runtime.h>
#include <math_constants.h>

typedef unsigned long long ull;

// Problem constants
#define NROWS 262144
#define DIMQ  128
#define MFEAT 256
#define SCALE 0.29730177875068026f   // 128^-0.25
#define INV_SQRT_M 0.0625f           // 1/sqrt(256)
#define PHI_EPS 1e-4f

// GEMM tiling: BM=64 rows x BN=256 (full width), 256 threads, warp owns 8 rows,
// lane owns cols [lane*8, lane*8+8). K=128 streamed in 8 chunks of 16.
#define BM 64
#define GEMM_THREADS 256
#define GEMM_BLOCKS (NROWS / BM)            // 4096
#define SX_STRIDE 132                       // 128 + 4 pad (row-major X tile)
#define OM_CHUNK_FLOATS (16 * MFEAT)        // 4096
#define SMEM_FLOATS (BM * SX_STRIDE + 2 * OM_CHUNK_FLOATS)
#define SMEM_BYTES  (SMEM_FLOATS * 4)       // 66560 B -> 2 CTAs/SM

// kp pass
#define KP_BLOCKS 1024
#define KP_ROWS_PER_BLOCK (NROWS / KP_BLOCKS)   // 256

// Scratch (device globals: allocation-free). g_UK holds U'_K then Kp.
__device__ float g_UK[(size_t)NROWS * MFEAT];
__device__ float g_part[KP_BLOCKS * MFEAT];
__device__ float g_ksum[MFEAT];
__device__ unsigned g_kmax_bits;

// Monotonic float<->uint encoding for atomicMax on floats
__device__ __forceinline__ unsigned fenc(float f) {
    unsigned u = __float_as_uint(f);
    return (u >> 31) ? ~u : (u | 0x80000000u);
}
__device__ __forceinline__ float fdec(unsigned u) {
    return (u >> 31) ? __uint_as_float(u & 0x7fffffffu) : __uint_as_float(~u);
}

// Packed fp32x2 FMA (Blackwell FFMA2 — only reachable via PTX)
__device__ __forceinline__ ull fma2(ull a, ull b, ull c) {
    ull d;
    asm("fma.rn.f32x2 %0, %1, %2, %3;" : "=l"(d) : "l"(a), "l"(b), "l"(c));
    return d;
}
__device__ __forceinline__ ull pack2(float lo, float hi) {
    ull r;
    asm("mov.b64 %0, {%1, %2};" : "=l"(r) : "r"(__float_as_uint(lo)), "r"(__float_as_uint(hi)));
    return r;
}
__device__ __forceinline__ void unpack2(ull p, float& lo, float& hi) {
    unsigned a, b;
    asm("mov.b64 {%0, %1}, %2;" : "=r"(a), "=r"(b) : "l"(p));
    lo = __uint_as_float(a);
    hi = __uint_as_float(b);
}

__global__ void init_kernel() { g_kmax_bits = 0u; }

// ---------------------------------------------------------------------------
// Fused GEMM: U = (X*SCALE) @ omega, h folded in.
//  IS_K: store U-h to g_UK, track global max of raw U (atomicMax, deterministic).
// !IS_K: full Q epilogue in-registers: row-max, Qp, w=<Qp,Kp>, nrm=<Qp,ksum>,
//        out = (w/nrm)*V. No U_Q scratch traffic at all.
// ---------------------------------------------------------------------------
template <bool IS_K>
__global__ __launch_bounds__(GEMM_THREADS, 2)
void gemm_kernel(const float* __restrict__ X,
                 const float* __restrict__ omega,
                 const float* __restrict__ V,
                 float* __restrict__ out)
{
    extern __shared__ float smem[];
    float* sX  = smem;                       // [64][132] row-major, scaled
    float* sOm = smem + BM * SX_STRIDE;      // [2][16][256]

    const int tid  = threadIdx.x;
    const int lane = tid & 31;
    const int w    = tid >> 5;               // warp 0..7 -> rows w*8..w*8+7
    const size_t row0 = (size_t)blockIdx.x * BM;

    // Load X tile (scaled), coalesced; 8 float4 per thread.
    {
        const float4* Xg = (const float4*)(X + row0 * DIMQ);
        #pragma unroll
        for (int q = 0; q < 8; q++) {
            int f = tid + q * GEMM_THREADS;  // f4 index: r = f/32, c4 = f%32
            float4 v = Xg[f];
            v.x *= SCALE; v.y *= SCALE; v.z *= SCALE; v.w *= SCALE;
            int r = f >> 5, c4 = f & 31;
            *(float4*)(sX + r * SX_STRIDE + c4 * 4) = v;
        }
    }

    // Prefetch omega chunk 0 into registers (4 float4 / thread)
    float4 pf[4];
    {
        const float4* Og = (const float4*)omega;
        #pragma unroll
        for (int q = 0; q < 4; q++) pf[q] = Og[tid + q * GEMM_THREADS];
    }
    __syncthreads();

    // h per warp row (all lanes end up with h[i]); conflict-free LDS.
    float h[8];
    #pragma unroll
    for (int i = 0; i < 8; i++) {
        const float* xr = sX + (size_t)(w * 8 + i) * SX_STRIDE;
        float s = 0.f;
        #pragma unroll
        for (int c = 0; c < 4; c++) { float v = xr[lane + c * 32]; s = fmaf(v, v, s); }
        #pragma unroll
        for (int o = 16; o > 0; o >>= 1) s += __shfl_xor_sync(0xffffffffu, s, o);
        h[i] = 0.5f * s;
    }

    // Accumulators: acc[i][jp] = (u[row i][lane*8+2jp], u[row i][lane*8+2jp+1])
    ull acc[8][4];
    #pragma unroll
    for (int i = 0; i < 8; i++)
        #pragma unroll
        for (int jp = 0; jp < 4; jp++) acc[i][jp] = 0ull;

    // Mainloop: 8 chunks of BK=16, double-buffered omega.
    #pragma unroll 1
    for (int chunk = 0; chunk < 8; chunk++) {
        float* so = sOm + (chunk & 1) * OM_CHUNK_FLOATS;
        // Commit prefetched chunk to smem (coalesced, conflict-free).
        #pragma unroll
        for (int q = 0; q < 4; q++)
            *(float4*)(so + (size_t)(tid + q * GEMM_THREADS) * 4) = pf[q];
        __syncthreads();

        // Issue next chunk's global loads early (hidden under compute).
        if (chunk < 7) {
            const float4* Og = (const float4*)(omega + (size_t)(chunk + 1) * 16 * MFEAT);
            #pragma unroll
            for (int q = 0; q < 4; q++) pf[q] = Og[tid + q * GEMM_THREADS];
        }

        #pragma unroll
        for (int kk = 0; kk < 16; kk++) {
            const int kg = chunk * 16 + kk;
            const ulonglong2* bq =
                (const ulonglong2*)(so + kk * MFEAT + lane * 8);
            ulonglong2 bA = bq[0], bB = bq[1];
            #pragma unroll
            for (int i = 0; i < 8; i++) {
                float a = sX[(size_t)(w * 8 + i) * SX_STRIDE + kg];  // broadcast LDS
                ull ad = pack2(a, a);
                acc[i][0] = fma2(ad, bA.x, acc[i][0]);
                acc[i][1] = fma2(ad, bA.y, acc[i][1]);
                acc[i][2] = fma2(ad, bB.x, acc[i][2]);
                acc[i][3] = fma2(ad, bB.y, acc[i][3]);
            }
        }
        __syncthreads();
    }

    if (IS_K) {
        // --- K epilogue: store U-h coalesced, track raw-U global max ---
        float umax = -CUDART_INF_F;
        #pragma unroll
        for (int i = 0; i < 8; i++) {
            float u[8];
            #pragma unroll
            for (int jp = 0; jp < 4; jp++) unpack2(acc[i][jp], u[2 * jp], u[2 * jp + 1]);
            #pragma unroll
            for (int j = 0; j < 8; j++) umax = fmaxf(umax, u[j]);
            const float hi_ = h[i];
            const size_t row = row0 + w * 8 + i;
            float4* dst = (float4*)(g_UK + row * MFEAT + lane * 8);
            dst[0] = make_float4(u[0] - hi_, u[1] - hi_, u[2] - hi_, u[3] - hi_);
            dst[1] = make_float4(u[4] - hi_, u[5] - hi_, u[6] - hi_, u[7] - hi_);
        }
        #pragma unroll
        for (int o = 16; o > 0; o >>= 1)
            umax = fmaxf(umax, __shfl_xor_sync(0xffffffffu, umax, o));
        if (lane == 0) atomicMax(&g_kmax_bits, fenc(umax));
    } else {
        // --- Q epilogue: softmax-feature + weighting + output, in-registers ---
        float ks[8];
        {
            const float4* kg = (const float4*)(g_ksum + lane * 8);
            float4 k0 = kg[0], k1 = kg[1];
            ks[0] = k0.x; ks[1] = k0.y; ks[2] = k0.z; ks[3] = k0.w;
            ks[4] = k1.x; ks[5] = k1.y; ks[6] = k1.z; ks[7] = k1.w;
        }
        #pragma unroll
        for (int i = 0; i < 8; i++) {
            float u[8];
            #pragma unroll
            for (int jp = 0; jp < 4; jp++) unpack2(acc[i][jp], u[2 * jp], u[2 * jp + 1]);
            const float hi_ = h[i];
            #pragma unroll
            for (int j = 0; j < 8; j++) u[j] -= hi_;

            float m = u[0];
            #pragma unroll
            for (int j = 1; j < 8; j++) m = fmaxf(m, u[j]);
            #pragma unroll
            for (int o = 16; o > 0; o >>= 1)
                m = fmaxf(m, __shfl_xor_sync(0xffffffffu, m, o));

            const size_t row = row0 + w * 8 + i;
            const float4* kpg = (const float4*)(g_UK + row * MFEAT + lane * 8);
            float4 kp0 = kpg[0], kp1 = kpg[1];
            float kp[8] = { kp0.x, kp0.y, kp0.z, kp0.w, kp1.x, kp1.y, kp1.z, kp1.w };

            float wv = 0.f, nrm = 0.f;
            #pragma unroll
            for (int j = 0; j < 8; j++) {
                float qp = (__expf(u[j] - m) + PHI_EPS) * INV_SQRT_M;
                wv  = fmaf(qp, kp[j], wv);
                nrm = fmaf(qp, ks[j], nrm);
            }
            #pragma unroll
            for (int o = 16; o > 0; o >>= 1) {
                wv  += __shfl_xor_sync(0xffffffffu, wv, o);
                nrm += __shfl_xor_sync(0xffffffffu, nrm, o);
            }
            const float scale = wv / (nrm + 1e-8f);

            const size_t vb = row * DIMQ + lane;
            #pragma unroll
            for (int c = 0; c < 4; c++)
                out[vb + c * 32] = scale * V[vb + c * 32];
        }
    }
}

// ---------------------------------------------------------------------------
// kp: Kp = (exp(U' - gmax) + eps)/sqrt(m), overwrite g_UK, per-block column
// partial sums (deterministic). Already at DRAM roofline (~86us).
// ---------------------------------------------------------------------------
__global__ __launch_bounds__(MFEAT)
void kp_kernel()
{
    const int tid = threadIdx.x;
    const float gmax = fdec(g_kmax_bits);
    const size_t base = (size_t)blockIdx.x * KP_ROWS_PER_BLOCK * MFEAT + tid;

    float psum = 0.f;
    #pragma unroll 4
    for (int r = 0; r < KP_ROWS_PER_BLOCK; r++) {
        size_t idx = base + (size_t)r * MFEAT;
        float u = g_UK[idx];
        float kp = (__expf(u - gmax) + PHI_EPS) * INV_SQRT_M;
        g_UK[idx] = kp;
        psum += kp;
    }
    g_part[blockIdx.x * MFEAT + tid] = psum;
}

// 1 block, 1024 threads: 4 slices x 256 columns, then combine.
__global__ __launch_bounds__(1024)
void ksum_kernel()
{
    __shared__ float red[4][MFEAT];
    const int col = threadIdx.x & (MFEAT - 1);
    const int slice = threadIdx.x >> 8;
    const int per = KP_BLOCKS / 4;

    float s = 0.f;
    #pragma unroll 8
    for (int b = 0; b < per; b++)
        s += g_part[(slice * per + b) * MFEAT + col];
    red[slice][col] = s;
    __syncthreads();
    if (slice == 0)
        g_ksum[col] = red[0][col] + red[1][col] + red[2][col] + red[3][col];
}

extern "C" void kernel_launch(void* const* d_in, const int* in_sizes, int n_in,
                              void* d_out, int out_size)
{
    const float* Q     = (const float*)d_in[0];
    const float* K     = (const float*)d_in[1];
    const float* V     = (const float*)d_in[2];
    const float* omega = (const float*)d_in[3];
    float* out = (float*)d_out;

    cudaFuncSetAttribute(gemm_kernel<true>,
                         cudaFuncAttributeMaxDynamicSharedMemorySize, SMEM_BYTES);
    cudaFuncSetAttribute(gemm_kernel<false>,
                         cudaFuncAttributeMaxDynamicSharedMemorySize, SMEM_BYTES);

    init_kernel<<<1, 1>>>();
    gemm_kernel<true ><<<GEMM_BLOCKS, GEMM_THREADS, SMEM_BYTES>>>(K, omega, nullptr, nullptr);
    kp_kernel<<<KP_BLOCKS, MFEAT>>>();
    ksum_kernel<<<1, 1024>>>();
    gemm_kernel<false><<<GEMM_BLOCKS, GEMM_THREADS, SMEM_BYTES>>>(Q, omega, V, out);
}